// round 1
// baseline (speedup 1.0000x reference)
#include <cuda_runtime.h>

#define SQ 1024   // sequence length (32*32)
#define CC 256    // QDIM == KDIM
#define EE 512    // EMBED
#define BB 8      // batch
#define HH 8      // heads
#define DD 64     // head dim

// Scratch: Q/K/V in per-batch (E, S) layout. 16 MB each.
__device__ float g_Q[BB * EE * SQ];
__device__ float g_K[BB * EE * SQ];
__device__ float g_V[BB * EE * SQ];

// ---------------------------------------------------------------------------
// Projection GEMM: Y[e][s] = sum_c W[e][c] * X[c][s] + bias[e]
// One CTA computes a 128(E) x 128(S) tile; BK=16; 256 threads, 8x8 per thread.
// grid = (S/128, E/128, B*3)  with z -> (batch, which projection)
// ---------------------------------------------------------------------------
__global__ __launch_bounds__(256) void proj_kernel(
    const float* __restrict__ q_in, const float* __restrict__ k_in,
    const float* __restrict__ wq, const float* __restrict__ biasq,
    const float* __restrict__ wk, const float* __restrict__ biask,
    const float* __restrict__ wv, const float* __restrict__ biasv)
{
    const int z = blockIdx.z;
    const int b = z / 3;
    const int p = z % 3;
    const float* X    = (p == 0 ? q_in : k_in) + (size_t)b * CC * SQ;
    const float* W    = (p == 0) ? wq : (p == 1 ? wk : wv);
    const float* bias = (p == 0) ? biasq : (p == 1 ? biask : biasv);
    float* Y = (p == 0 ? g_Q : (p == 1 ? g_K : g_V)) + (size_t)b * EE * SQ;

    const int m0 = blockIdx.y * 128;  // E tile
    const int n0 = blockIdx.x * 128;  // S tile

    __shared__ __align__(16) float As[16][132];  // A^T: [k][m], padded
    __shared__ __align__(16) float Bs[16][128];  // [k][n]

    const int tid = threadIdx.x;
    const int tm = (tid / 16) * 8;
    const int tn = (tid % 16) * 8;

    float acc[8][8];
    #pragma unroll
    for (int i = 0; i < 8; i++)
        #pragma unroll
        for (int j = 0; j < 8; j++) acc[i][j] = 0.0f;

    for (int k0 = 0; k0 < CC; k0 += 16) {
        // Load A tile (W: 128 x 16) transposed into As, and B tile (X: 16 x 128).
        #pragma unroll
        for (int r = 0; r < 2; r++) {
            int t = tid + r * 256;
            // A: 512 float4 total
            int m  = t >> 2;
            int kq = (t & 3) * 4;
            float4 a = *(const float4*)(W + (size_t)(m0 + m) * CC + k0 + kq);
            As[kq + 0][m] = a.x;
            As[kq + 1][m] = a.y;
            As[kq + 2][m] = a.z;
            As[kq + 3][m] = a.w;
            // B: 512 float4 total
            int kb = t >> 5;
            int nq = (t & 31) * 4;
            *(float4*)(&Bs[kb][nq]) =
                *(const float4*)(X + (size_t)(k0 + kb) * SQ + n0 + nq);
        }
        __syncthreads();

        #pragma unroll
        for (int k = 0; k < 16; k++) {
            float a[8], bf[8];
            *(float4*)&a[0]  = *(const float4*)&As[k][tm];
            *(float4*)&a[4]  = *(const float4*)&As[k][tm + 4];
            *(float4*)&bf[0] = *(const float4*)&Bs[k][tn];
            *(float4*)&bf[4] = *(const float4*)&Bs[k][tn + 4];
            #pragma unroll
            for (int i = 0; i < 8; i++)
                #pragma unroll
                for (int j = 0; j < 8; j++)
                    acc[i][j] = fmaf(a[i], bf[j], acc[i][j]);
        }
        __syncthreads();
    }

    #pragma unroll
    for (int i = 0; i < 8; i++) {
        float bv2 = __ldg(bias + m0 + tm + i);
        float* yrow = Y + (size_t)(m0 + tm + i) * SQ + n0 + tn;
        float4 o0, o1;
        o0.x = acc[i][0] + bv2; o0.y = acc[i][1] + bv2;
        o0.z = acc[i][2] + bv2; o0.w = acc[i][3] + bv2;
        o1.x = acc[i][4] + bv2; o1.y = acc[i][5] + bv2;
        o1.z = acc[i][6] + bv2; o1.w = acc[i][7] + bv2;
        *(float4*)yrow       = o0;
        *(float4*)(yrow + 4) = o1;
    }
}

// ---------------------------------------------------------------------------
// Causal flash attention. One CTA = one (batch, head, 64-row query block).
// Q/K/V read from (E,S) layout; output written directly to (B,E,S) = d_out.
// 256 threads; thread (ti,tj) owns a 4x4 score microtile and a 4(i)x4(d)
// output microtile. Smem exactly 48KB: Qs + SP (K tile aliased with P tile)
// + Vt (XOR-swizzled 16B chunks for conflict-free column reads).
// ---------------------------------------------------------------------------
__global__ __launch_bounds__(256) void attn_kernel(float* __restrict__ out)
{
    const int qb = blockIdx.x;   // 0..15
    const int h  = blockIdx.y;
    const int b  = blockIdx.z;

    const float* Qh = g_Q + ((size_t)b * EE + h * DD) * SQ;  // [d][s]
    const float* Kh = g_K + ((size_t)b * EE + h * DD) * SQ;
    const float* Vh = g_V + ((size_t)b * EE + h * DD) * SQ;
    float*       Oh = out + ((size_t)b * EE + h * DD) * SQ;

    __shared__ __align__(16) float Qs[64][64];  // [d][i] (later reused for O^T)
    __shared__ __align__(16) float SP[64][64];  // K tile [d][j], then P tile [i][j]
    __shared__ __align__(16) float Vt[64][64];  // [d][j], chunk-swizzled

    const int tid = threadIdx.x;
    const int ti = tid / 16, tj = tid % 16;
    const int i0 = ti * 4;           // score / output rows
    const int j0 = tj * 4;           // score cols; also output d-cols (d0 == j0)
    const int s0 = qb * 64;

    // Load Q tile (scaled by 1/sqrt(D) = 0.125)
    for (int t = tid; t < 64 * 16; t += 256) {
        int d = t >> 4, iq = (t & 15) * 4;
        float4 q = *(const float4*)(Qh + (size_t)d * SQ + s0 + iq);
        q.x *= 0.125f; q.y *= 0.125f; q.z *= 0.125f; q.w *= 0.125f;
        *(float4*)&Qs[d][iq] = q;
    }

    float m_i[4], l_i[4], o_acc[4][4];
    #pragma unroll
    for (int ii = 0; ii < 4; ii++) {
        m_i[ii] = -1e30f;
        l_i[ii] = 0.0f;
        #pragma unroll
        for (int dd = 0; dd < 4; dd++) o_acc[ii][dd] = 0.0f;
    }

    const int nkb = qb + 1;  // causal: only blocks <= qb
    for (int kb = 0; kb < nkb; kb++) {
        __syncthreads();  // prev AV reads of SP/Vt done (also orders Qs writes)
        const int c0 = kb * 64;
        for (int t = tid; t < 64 * 16; t += 256) {
            int d = t >> 4, jq = t & 15;
            *(float4*)&SP[d][jq * 4] =
                *(const float4*)(Kh + (size_t)d * SQ + c0 + jq * 4);
            float4 v = *(const float4*)(Vh + (size_t)d * SQ + c0 + jq * 4);
            *(float4*)&Vt[d][((jq ^ (d >> 2)) & 15) * 4] = v;
        }
        __syncthreads();

        // ---- scores: sc[ii][jj] = sum_d Qs[d][i0+ii] * K[d][j0+jj]
        float sc[4][4];
        #pragma unroll
        for (int ii = 0; ii < 4; ii++)
            #pragma unroll
            for (int jj = 0; jj < 4; jj++) sc[ii][jj] = 0.0f;

        #pragma unroll 16
        for (int d = 0; d < 64; d++) {
            float4 q4 = *(const float4*)&Qs[d][i0];
            float4 k4 = *(const float4*)&SP[d][j0];
            float qa[4] = {q4.x, q4.y, q4.z, q4.w};
            float ka[4] = {k4.x, k4.y, k4.z, k4.w};
            #pragma unroll
            for (int ii = 0; ii < 4; ii++)
                #pragma unroll
                for (int jj = 0; jj < 4; jj++)
                    sc[ii][jj] = fmaf(qa[ii], ka[jj], sc[ii][jj]);
        }

        // ---- causal mask on diagonal block
        if (kb == qb) {
            #pragma unroll
            for (int ii = 0; ii < 4; ii++)
                #pragma unroll
                for (int jj = 0; jj < 4; jj++)
                    if (j0 + jj > i0 + ii) sc[ii][jj] = -1e30f;
        }

        // ---- online softmax (row stats shared across the 16 tj lanes)
        #pragma unroll
        for (int ii = 0; ii < 4; ii++) {
            float mx = fmaxf(fmaxf(sc[ii][0], sc[ii][1]),
                             fmaxf(sc[ii][2], sc[ii][3]));
            #pragma unroll
            for (int off = 8; off > 0; off >>= 1)
                mx = fmaxf(mx, __shfl_xor_sync(0xffffffffu, mx, off));
            float mnew = fmaxf(m_i[ii], mx);
            float corr = __expf(m_i[ii] - mnew);
            m_i[ii] = mnew;
            float rs = 0.0f;
            #pragma unroll
            for (int jj = 0; jj < 4; jj++) {
                float pe = __expf(sc[ii][jj] - mnew);
                sc[ii][jj] = pe;
                rs += pe;
            }
            #pragma unroll
            for (int off = 8; off > 0; off >>= 1)
                rs += __shfl_xor_sync(0xffffffffu, rs, off);
            l_i[ii] = l_i[ii] * corr + rs;
            #pragma unroll
            for (int dd = 0; dd < 4; dd++) o_acc[ii][dd] *= corr;
        }

        __syncthreads();  // all K-tile reads done before P overwrites SP
        #pragma unroll
        for (int ii = 0; ii < 4; ii++)
            *(float4*)&SP[i0 + ii][j0] =
                make_float4(sc[ii][0], sc[ii][1], sc[ii][2], sc[ii][3]);
        __syncthreads();

        // ---- AV: o_acc[ii][dd] += sum_j P[i0+ii][j] * V[j][j0+dd]
        #pragma unroll 4
        for (int jq = 0; jq < 16; jq++) {
            float4 pv[4], vv[4];
            #pragma unroll
            for (int ii = 0; ii < 4; ii++)
                pv[ii] = *(const float4*)&SP[i0 + ii][jq * 4];
            #pragma unroll
            for (int dd = 0; dd < 4; dd++)
                vv[dd] = *(const float4*)&Vt[j0 + dd][((jq ^ tj) & 15) * 4];
            #pragma unroll
            for (int ii = 0; ii < 4; ii++)
                #pragma unroll
                for (int dd = 0; dd < 4; dd++)
                    o_acc[ii][dd] = fmaf(pv[ii].x, vv[dd].x,
                                    fmaf(pv[ii].y, vv[dd].y,
                                    fmaf(pv[ii].z, vv[dd].z,
                                    fmaf(pv[ii].w, vv[dd].w, o_acc[ii][dd]))));
        }
    }

    // ---- normalize, stage O^T into Qs (chunk-swizzled), write coalesced
    float inv[4];
    #pragma unroll
    for (int ii = 0; ii < 4; ii++) inv[ii] = 1.0f / l_i[ii];

    #pragma unroll
    for (int dd = 0; dd < 4; dd++) {
        int d = j0 + dd;
        float4 o;
        o.x = o_acc[0][dd] * inv[0];
        o.y = o_acc[1][dd] * inv[1];
        o.z = o_acc[2][dd] * inv[2];
        o.w = o_acc[3][dd] * inv[3];
        *(float4*)&Qs[d][((ti ^ (d >> 2)) & 15) * 4] = o;
    }
    __syncthreads();

    for (int t = tid; t < 64 * 16; t += 256) {
        int d = t >> 4, iq = t & 15;
        float4 v = *(const float4*)&Qs[d][((iq ^ (d >> 2)) & 15) * 4];
        *(float4*)(Oh + (size_t)d * SQ + s0 + iq * 4) = v;
    }
}

// ---------------------------------------------------------------------------
extern "C" void kernel_launch(void* const* d_in, const int* in_sizes, int n_in,
                              void* d_out, int out_size)
{
    const float* query = (const float*)d_in[0];
    const float* key   = (const float*)d_in[1];
    const float* Wq    = (const float*)d_in[2];
    const float* bq    = (const float*)d_in[3];
    const float* Wk    = (const float*)d_in[4];
    const float* bk    = (const float*)d_in[5];
    const float* Wv    = (const float*)d_in[6];
    const float* bv    = (const float*)d_in[7];

    dim3 g1(SQ / 128, EE / 128, BB * 3);
    proj_kernel<<<g1, 256>>>(query, key, Wq, bq, Wk, bk, Wv, bv);

    dim3 g2(SQ / 64, HH, BB);
    attn_kernel<<<g2, 256>>>((float*)d_out);
}